// round 3
// baseline (speedup 1.0000x reference)
#include <cuda_runtime.h>
#include <cuda_bf16.h>

// 3D LUT trilinear interpolation.
// x:   [8, 3, 1920, 1080] f32
// lut: [3, 33, 33, 33]    f32  (indexed [chan, b, g, r], r fastest)
// out: [8, 3, 1920, 1080] f32  (reference transposes (3,8,H,W)->(8,3,H,W),
//                               i.e. SAME layout as x)
//
// Strategy: random LUT gathers are poison for L1tex (divergent LDG = one
// wavefront per distinct sector). One channel's LUT (143,748 B) fits in
// dynamic smem, and random LDS only costs bank-conflict degree (~3).
// Each CTA owns (channel, pixel-chunk): stage channel LUT in smem,
// stream x as float4, gather 8 corners per pixel via LDS, lerp r->g->b.
// chan = blockIdx.x % 3 co-schedules the 3 channel-CTAs of a chunk in the
// same wave -> x chunk read from DRAM once, L2-hit twice.

#define NPLANE   (1920 * 1080)        // 2,073,600 (divisible by 4)
#define NBATCH   8
#define NPIX     (NBATCH * NPLANE)    // 16,588,800
#define LUTC     35937                // 33^3
#define THREADS  1024
#define NCHUNK   148
#define SMEM_BYTES (LUTC * 4)         // 143,748 B

__device__ __forceinline__ float interp1(const float* __restrict__ slut,
                                         float r, float g, float b,
                                         float invbin) {
    float xr = r * invbin;
    float xg = g * invbin;
    float xb = b * invbin;
    int ir = min(max(__float2int_rd(xr), 0), 31);
    int ig = min(max(__float2int_rd(xg), 0), 31);
    int ib = min(max(__float2int_rd(xb), 0), 31);
    float rd = xr - (float)ir;
    float gd = xg - (float)ig;
    float bd = xb - (float)ib;
    int base = ib * 1089 + ig * 33 + ir;

    float v000 = slut[base];
    float v001 = slut[base + 1];
    float v010 = slut[base + 33];
    float v011 = slut[base + 34];
    float v100 = slut[base + 1089];
    float v101 = slut[base + 1090];
    float v110 = slut[base + 1122];
    float v111 = slut[base + 1123];

    float c00 = fmaf(rd, v001 - v000, v000);
    float c01 = fmaf(rd, v011 - v010, v010);
    float c10 = fmaf(rd, v101 - v100, v100);
    float c11 = fmaf(rd, v111 - v110, v110);
    float c0  = fmaf(gd, c01 - c00, c00);
    float c1  = fmaf(gd, c11 - c10, c10);
    return fmaf(bd, c1 - c0, c0);
}

__global__ void __launch_bounds__(THREADS, 1)
lut3d_kernel(const float* __restrict__ lut,
             const float* __restrict__ x,
             float* __restrict__ out) {
    extern __shared__ float slut[];

    const int chan  = blockIdx.x % 3;
    const int chunk = blockIdx.x / 3;

    // Stage this channel's LUT into shared memory.
    const float* __restrict__ lc = lut + chan * LUTC;
    #pragma unroll 4
    for (int i = threadIdx.x; i < LUTC; i += THREADS)
        slut[i] = lc[i];
    __syncthreads();

    const float invbin = 32.0f / 1.000001f;  // 1/binsize

    const int ngroups = NPIX / 4;                      // 4,147,200 float4 groups
    const int per     = (ngroups + NCHUNK - 1) / NCHUNK;
    const int gbeg    = chunk * per;
    const int gend    = min(gbeg + per, ngroups);

    for (int gidx = gbeg + (int)threadIdx.x; gidx < gend; gidx += THREADS) {
        const int q    = gidx * 4;             // global pixel index
        const int bimg = q / NPLANE;           // batch (group never straddles)
        const int p    = q - bimg * NPLANE;

        const float* __restrict__ xb = x + (size_t)bimg * 3 * NPLANE + p;
        const float4 r4 = *(const float4*)(xb);
        const float4 g4 = *(const float4*)(xb + NPLANE);
        const float4 b4 = *(const float4*)(xb + 2 * NPLANE);

        float4 o;
        o.x = interp1(slut, r4.x, g4.x, b4.x, invbin);
        o.y = interp1(slut, r4.y, g4.y, b4.y, invbin);
        o.z = interp1(slut, r4.z, g4.z, b4.z, invbin);
        o.w = interp1(slut, r4.w, g4.w, b4.w, invbin);

        // out has the SAME [8,3,H,W] layout as x: batch-major, then channel.
        *(float4*)(out + (size_t)bimg * 3 * NPLANE + (size_t)chan * NPLANE + p) = o;
    }
}

extern "C" void kernel_launch(void* const* d_in, const int* in_sizes, int n_in,
                              void* d_out, int out_size) {
    const float* lut = (const float*)d_in[0];   // 3*33^3 = 107,811 floats
    const float* x   = (const float*)d_in[1];   // 49,766,400 floats
    float* out       = (float*)d_out;           // 49,766,400 floats

    cudaFuncSetAttribute(lut3d_kernel,
                         cudaFuncAttributeMaxDynamicSharedMemorySize,
                         SMEM_BYTES);
    lut3d_kernel<<<3 * NCHUNK, THREADS, SMEM_BYTES>>>(lut, x, out);
}

// round 5
// speedup vs baseline: 1.4833x; 1.4833x over previous
#include <cuda_runtime.h>
#include <cuda_bf16.h>
#include <cuda_fp16.h>

// 3D LUT trilinear interpolation.
// x:   [8, 3, 1920, 1080] f32
// lut: [3, 33, 33, 33]    f32  (indexed [chan, b, g, r], r fastest)
// out: [8, 3, 1920, 1080] f32  (same layout as x)
//
// R3: the R2 profile showed shared/L1 pipe at 85% SOL (8 random LDS.32 per
// pixel-channel, ~3.3x bank-conflict degree) with DRAM at 22%. Halve the
// LDS count by packing each r-adjacent corner pair (v[r], v[r+1]) as one
// half2: table = 33*33*32 half2 = 139,392 B (fits smem), 4 LDS.32/pixel.
// Unpack to fp32 and lerp in fp32 so the only added error is the one-time
// fp16 quantization of LUT entries (<= 2^-11 relative ~ 4.9e-4, convex
// combination preserves the bound; norm rel_err lands ~3e-4 < 1e-3).

#define NPLANE   (1920 * 1080)        // 2,073,600 (divisible by 4)
#define NBATCH   8
#define NPIX     (NBATCH * NPLANE)    // 16,588,800
#define LUTC     35937                // 33^3 (fp32 source entries per channel)
#define PACKN    (33 * 33 * 32)       // 34,848 packed half2 entries
#define G_STRIDE 32                   // packed stride per g step
#define B_STRIDE (33 * 32)            // 1056, packed stride per b step
#define THREADS  1024
#define NCHUNK   148
#define SMEM_BYTES (PACKN * 4)        // 139,392 B

__device__ __forceinline__ float interp1(const unsigned* __restrict__ slut2,
                                         float r, float g, float b,
                                         float invbin) {
    float xr = r * invbin;
    float xg = g * invbin;
    float xb = b * invbin;
    int ir = min(max(__float2int_rd(xr), 0), 31);
    int ig = min(max(__float2int_rd(xg), 0), 31);
    int ib = min(max(__float2int_rd(xb), 0), 31);
    float rd = xr - (float)ir;
    float gd = xg - (float)ig;
    float bd = xb - (float)ib;
    int base = ib * B_STRIDE + ig * G_STRIDE + ir;

    unsigned p00 = slut2[base];                         // (v000, v001)
    unsigned p01 = slut2[base + G_STRIDE];              // (v010, v011)
    unsigned p10 = slut2[base + B_STRIDE];              // (v100, v101)
    unsigned p11 = slut2[base + B_STRIDE + G_STRIDE];   // (v110, v111)

    float2 f00 = __half22float2(*(const __half2*)&p00);
    float2 f01 = __half22float2(*(const __half2*)&p01);
    float2 f10 = __half22float2(*(const __half2*)&p10);
    float2 f11 = __half22float2(*(const __half2*)&p11);

    float c00 = fmaf(rd, f00.y - f00.x, f00.x);
    float c01 = fmaf(rd, f01.y - f01.x, f01.x);
    float c10 = fmaf(rd, f10.y - f10.x, f10.x);
    float c11 = fmaf(rd, f11.y - f11.x, f11.x);
    float c0  = fmaf(gd, c01 - c00, c00);
    float c1  = fmaf(gd, c11 - c10, c10);
    return fmaf(bd, c1 - c0, c0);
}

__global__ void __launch_bounds__(THREADS, 1)
lut3d_kernel(const float* __restrict__ lut,
             const float* __restrict__ x,
             float* __restrict__ out) {
    extern __shared__ unsigned slut2[];

    const int chan  = blockIdx.x % 3;
    const int chunk = blockIdx.x / 3;

    // Build packed half2 table: slut2[(ib*33+ig)*32 + ir] = (v[r], v[r+1]).
    const float* __restrict__ lc = lut + chan * LUTC;
    for (int i = threadIdx.x; i < PACKN; i += THREADS) {
        int ir   = i & 31;
        int rest = i >> 5;             // ib*33 + ig
        int src  = rest * 33 + ir;     // ib*1089 + ig*33 + ir
        __half2 h = __floats2half2_rn(lc[src], lc[src + 1]);
        slut2[i] = *(const unsigned*)&h;
    }
    __syncthreads();

    const float invbin = 32.0f / 1.000001f;  // 1/binsize

    const int ngroups = NPIX / 4;
    const int per     = (ngroups + NCHUNK - 1) / NCHUNK;
    const int gbeg    = chunk * per;
    const int gend    = min(gbeg + per, ngroups);

    for (int gidx = gbeg + (int)threadIdx.x; gidx < gend; gidx += THREADS) {
        const int q    = gidx * 4;
        const int bimg = q / NPLANE;          // batch (group never straddles)
        const int p    = q - bimg * NPLANE;

        const float* __restrict__ xb = x + (size_t)bimg * 3 * NPLANE + p;
        const float4 r4 = *(const float4*)(xb);
        const float4 g4 = *(const float4*)(xb + NPLANE);
        const float4 b4 = *(const float4*)(xb + 2 * NPLANE);

        float4 o;
        o.x = interp1(slut2, r4.x, g4.x, b4.x, invbin);
        o.y = interp1(slut2, r4.y, g4.y, b4.y, invbin);
        o.z = interp1(slut2, r4.z, g4.z, b4.z, invbin);
        o.w = interp1(slut2, r4.w, g4.w, b4.w, invbin);

        *(float4*)(out + (size_t)bimg * 3 * NPLANE + (size_t)chan * NPLANE + p) = o;
    }
}

extern "C" void kernel_launch(void* const* d_in, const int* in_sizes, int n_in,
                              void* d_out, int out_size) {
    const float* lut = (const float*)d_in[0];
    const float* x   = (const float*)d_in[1];
    float* out       = (float*)d_out;

    cudaFuncSetAttribute(lut3d_kernel,
                         cudaFuncAttributeMaxDynamicSharedMemorySize,
                         SMEM_BYTES);
    lut3d_kernel<<<3 * NCHUNK, THREADS, SMEM_BYTES>>>(lut, x, out);
}